// round 10
// baseline (speedup 1.0000x reference)
#include <cuda_runtime.h>
#include <cuda_bf16.h>
#include <cstdint>

// FineMatching (P=512, R=S=128, K=3, THRESH=0.05, OR-combine, conditional).
// R10: R9 cluster structure + ALU cuts.
//   - Pair-insert top-3 (8 ops / 2 elems instead of 10), 2 accumulators.
//   - Redundant pre-exchange __syncthreads removed (arrive orders own writes).
//   2-CTA clusters, half-proposal per CTA (64 rows x 128 cols), cp.async fill,
//   DSMEM col-partial exchange, x-domain thresholds, __stcs stores.

#define PP 512
#define NT 256
#define XTHRESH (-2.99573227355f)   // ln(0.05)

struct Top3 { float v1, v2, v3; };

__device__ __forceinline__ void ins3(Top3& t, float v) {
    float t1 = fminf(t.v1, v);
    float t2 = fminf(t.v2, v);
    t.v1 = fmaxf(t.v1, v);
    t.v2 = fmaxf(t.v2, t1);
    t.v3 = fmaxf(t.v3, t2);
}

// Insert pair {a,b}: merge sorted (v1>=v2>=v3) with sorted (hi>=lo). 8 ops.
__device__ __forceinline__ void ins3p(Top3& t, float a, float b) {
    float hi = fmaxf(a, b);
    float lo = fminf(a, b);
    float o1 = fmaxf(t.v1, hi);
    float a2 = fminf(t.v1, hi);
    float m  = fmaxf(t.v2, lo);
    float o2 = fmaxf(a2, m);
    float o3 = fmaxf(fminf(a2, m), t.v3);
    t.v1 = o1;
    t.v2 = o2;
    t.v3 = o3;
}

__device__ __forceinline__ void merge(Top3& a, const Top3& b) {
    ins3(a, b.v1);
    ins3(a, b.v2);
    ins3(a, b.v3);
}

__device__ __forceinline__ void merge_xor1(Top3& t) {
    Top3 b;
    b.v1 = __shfl_xor_sync(0xffffffffu, t.v1, 1);
    b.v2 = __shfl_xor_sync(0xffffffffu, t.v2, 1);
    b.v3 = __shfl_xor_sync(0xffffffffu, t.v3, 1);
    merge(t, b);
}

#define T3INIT {-1e30f, -1e30f, -1e30f}

__device__ __forceinline__ float ld_peer_f32(uint32_t local_saddr, uint32_t peer_rank) {
    uint32_t ra;
    float v;
    asm volatile("mapa.shared::cluster.u32 %0, %1, %2;"
                 : "=r"(ra) : "r"(local_saddr), "r"(peer_rank));
    asm volatile("ld.shared::cluster.f32 %0, [%1];" : "=f"(v) : "r"(ra));
    return v;
}

__global__ __launch_bounds__(NT, 6) __cluster_dims__(2, 1, 1)
void fine_matching_kernel(
    const float4* __restrict__ msm4,        // [P,R,S] as float4 (raw log-scores)
    const unsigned int* __restrict__ refm,  // [P,R] 32-bit bool
    const uint4* __restrict__ srcm4,        // [P,S] 32-bit bool as uint4
    const float* __restrict__ ncs,          // [P]
    float4* __restrict__ out4,              // [score | corr] as float4
    int write_corr)
{
    __shared__ __align__(16) float tile[64 * 132];   // half-tile, pitch 132
    __shared__ float cp1[128], cp2[128], cp3[128];   // my col partial top-3
    __shared__ __align__(16) float colT[128];        // merged col thresholds
    __shared__ float2 rowInfo[64];                   // (rowTx, refmaskF)

    const int bid  = blockIdx.x;
    const int p    = bid >> 1;
    const int half = bid & 1;                        // == cluster rank
    const uint32_t peer = (uint32_t)(half ^ 1);
    const int tid  = threadIdx.x;
    const int lane = tid & 31;

    // ---- P0/P1: masks; half-tile fill via cp.async (8 x 16B in flight)
    if (tid < 64)
        rowInfo[tid].y = (refm[p * 128 + half * 64 + tid] != 0u) ? 1.0f : 0.0f;

    {
        const float4* g = msm4 + p * 4096 + half * 2048 + tid;
        uint32_t sp = (uint32_t)__cvta_generic_to_shared(
            (float4*)tile + (tid >> 5) * 33 + lane);
        #pragma unroll
        for (int k = 0; k < 8; k++) {
            asm volatile("cp.async.cg.shared.global [%0], [%1], 16;"
                         :: "r"(sp + k * (8 * 33 * 16)), "l"(g + k * NT));
        }
        asm volatile("cp.async.commit_group;");
        asm volatile("cp.async.wait_group 0;" ::: "memory");
    }
    __syncthreads();

    // ---- P2: local scans (threads 0..127 cols, 128..255 rows), pair-inserts
    if (tid < 128) {
        // 1 thread per column, 64 rows = 32 pairs, 2 interleaved accumulators
        const float* base = tile + tid;
        Top3 t0 = T3INIT, t1 = T3INIT;
        #pragma unroll
        for (int j = 0; j < 16; j++) {
            ins3p(t0, base[(4 * j + 0) * 132], base[(4 * j + 1) * 132]);
            ins3p(t1, base[(4 * j + 2) * 132], base[(4 * j + 3) * 132]);
        }
        merge(t0, t1);
        cp1[tid] = t0.v1;
        cp2[tid] = t0.v2;
        cp3[tid] = t0.v3;
    } else {
        // 2 threads per row (64 rows), LDS.128; half1 f4 20..31 then 16..19
        const int u  = tid - 128;
        const int r  = u >> 1;
        const int hf = u & 1;
        Top3 t0 = T3INIT, t1 = T3INIT;
        const float4* ra = (const float4*)tile + r * 33 + (hf ? 20 : 0);
        #pragma unroll
        for (int j = 0; j < 12; j++) {
            float4 v = ra[j];
            ins3p(t0, v.x, v.y);
            ins3p(t1, v.z, v.w);
        }
        const float4* rb = (const float4*)tile + r * 33 + (hf ? 16 : 12);
        #pragma unroll
        for (int j = 0; j < 4; j++) {
            float4 v = rb[j];
            ins3p(t0, v.x, v.y);
            ins3p(t1, v.z, v.w);
        }
        merge(t0, t1);
        merge_xor1(t0);
        if (!hf) rowInfo[r].x = t0.v3;
    }
    // no __syncthreads needed: each thread's own smem writes are ordered by
    // its cluster arrive; the local merge below reads only self-written cells.

    // ---- Exchange col partials with cluster peer, merge
    asm volatile("barrier.cluster.arrive.aligned;" ::: "memory");
    asm volatile("barrier.cluster.wait.aligned;" ::: "memory");

    if (tid < 128) {
        Top3 t;
        t.v1 = cp1[tid];
        t.v2 = cp2[tid];
        t.v3 = cp3[tid];
        uint32_t a1 = (uint32_t)__cvta_generic_to_shared(cp1 + tid);
        uint32_t a2 = (uint32_t)__cvta_generic_to_shared(cp2 + tid);
        uint32_t a3 = (uint32_t)__cvta_generic_to_shared(cp3 + tid);
        float p1 = ld_peer_f32(a1, peer);
        float p2 = ld_peer_f32(a2, peer);
        float p3 = ld_peer_f32(a3, peer);
        ins3(t, p1);
        ins3p(t, p2, p3);
        colT[tid] = t.v3;
    }
    __syncthreads();
    // done touching peer smem after this point; arrive now, wait at kernel end
    asm volatile("barrier.cluster.arrive.aligned;" ::: "memory");

    // ---- P3: dense output for my 64 rows; __stcs streaming stores
    const float scale = 0.5f * __ldg(ncs + p);
    const float4 cT = *(const float4*)(colT + 4 * lane);
    const uint4 smv = srcm4[p * 32 + lane];
    const float m0 = (smv.x != 0u) ? 1.f : 0.f;
    const float m1 = (smv.y != 0u) ? 1.f : 0.f;
    const float m2 = (smv.z != 0u) ? 1.f : 0.f;
    const float m3 = (smv.w != 0u) ? 1.f : 0.f;

    const float4* tp  = (const float4*)tile + (tid >> 5) * 33 + lane;
    const float2* rip = rowInfo + (tid >> 5);
    float4* sco = out4 + (size_t)p * 4096 + half * 2048 + tid;
    float4* cor = sco + (size_t)PP * 4096;

    if (write_corr) {
        #pragma unroll
        for (int k = 0; k < 8; k++) {
            float2 ri = rip[8 * k];             // warp-uniform (rowTx, refmaskF)
            float4 x  = tp[k * 8 * 33];

            bool ax = x.x >= ri.x, bx = x.x >= cT.x;
            bool ay = x.y >= ri.x, by = x.y >= cT.y;
            bool az = x.z >= ri.x, bz = x.z >= cT.z;
            bool aw = x.w >= ri.x, bw = x.w >= cT.w;

            float svx = scale * __expf(x.x), svy = scale * __expf(x.y);
            float svz = scale * __expf(x.z), svw = scale * __expf(x.w);

            float4 s4;
            s4.x = (ax ? svx : 0.f) + (bx ? svx : 0.f);
            s4.y = (ay ? svy : 0.f) + (by ? svy : 0.f);
            s4.z = (az ? svz : 0.f) + (bz ? svz : 0.f);
            s4.w = (aw ? svw : 0.f) + (bw ? svw : 0.f);
            __stcs(sco + k * NT, s4);

            float4 c4;
            c4.x = ((ax || bx) && x.x > XTHRESH) ? ri.y * m0 : 0.f;
            c4.y = ((ay || by) && x.y > XTHRESH) ? ri.y * m1 : 0.f;
            c4.z = ((az || bz) && x.z > XTHRESH) ? ri.y * m2 : 0.f;
            c4.w = ((aw || bw) && x.w > XTHRESH) ? ri.y * m3 : 0.f;
            __stcs(cor + k * NT, c4);
        }
    } else {
        #pragma unroll
        for (int k = 0; k < 8; k++) {
            float2 ri = rip[8 * k];
            float4 x  = tp[k * 8 * 33];
            bool ax = x.x >= ri.x, bx = x.x >= cT.x;
            bool ay = x.y >= ri.x, by = x.y >= cT.y;
            bool az = x.z >= ri.x, bz = x.z >= cT.z;
            bool aw = x.w >= ri.x, bw = x.w >= cT.w;
            float svx = scale * __expf(x.x), svy = scale * __expf(x.y);
            float svz = scale * __expf(x.z), svw = scale * __expf(x.w);
            float4 s4;
            s4.x = (ax ? svx : 0.f) + (bx ? svx : 0.f);
            s4.y = (ay ? svy : 0.f) + (by ? svy : 0.f);
            s4.z = (az ? svz : 0.f) + (bz ? svz : 0.f);
            s4.w = (aw ? svw : 0.f) + (bw ? svw : 0.f);
            __stcs(sco + k * NT, s4);
        }
    }

    // don't exit while peer may still read my cp arrays
    asm volatile("barrier.cluster.wait.aligned;" ::: "memory");
}

extern "C" void kernel_launch(void* const* d_in, const int* in_sizes, int n_in,
                              void* d_out, int out_size) {
    const float4* msm4       = (const float4*)d_in[0];
    const unsigned int* refm = (const unsigned int*)d_in[1];
    const uint4* srcm4       = (const uint4*)d_in[2];
    const float* ncs         = (const float*)d_in[3];
    float4* out4             = (float4*)d_out;

    const int prs = PP * 128 * 128;
    int write_corr = (out_size >= 2 * prs) ? 1 : 0;

    fine_matching_kernel<<<2 * PP, NT>>>(msm4, refm, srcm4, ncs, out4,
                                         write_corr);
}